// round 10
// baseline (speedup 1.0000x reference)
#include <cuda_runtime.h>
#include <stdint.h>

#define LATENT 64
#define HID    32
#define EDIM   4
#define N_NODES_MAX 100000
#define TILE_E 96
#define SD_STRIDE 68   // 64 + 4 pad
#define SH_STRIDE 36   // 32 + 4 pad

__device__ float g_P1[N_NODES_MAX * HID];
__device__ float g_PD[N_NODES_MAX * EDIM];
__device__ int   g_flag;   // 0 => edge_index int64, 1 => int32

__device__ __forceinline__ void ffma2(unsigned long long &acc,
                                      unsigned long long a,
                                      unsigned long long b) {
    asm("fma.rn.f32x2 %0, %1, %2, %0;" : "+l"(acc) : "l"(a), "l"(b));
}
__device__ __forceinline__ float2 unpack2(unsigned long long v) {
    float2 f;
    asm("mov.b64 {%0, %1}, %2;" : "=f"(f.x), "=f"(f.y) : "l"(v));
    return f;
}

// ---------------- dtype detection ----------------
__global__ void reset_flag_kernel() { g_flag = 0; }

// Sample the first n_probe int64 words (fits the buffer under both dtype
// interpretations). int32 storage => fused pairs exceed n_nodes virtually
// always; one warp-ballot atomic per warp max.
__global__ __launch_bounds__(256) void probe_kernel(
    const long long* __restrict__ e, int n_probe, int n_nodes)
{
    int i = blockIdx.x * 256 + threadIdx.x;
    bool bad = false;
    if (i < n_probe) {
        long long v = __ldg(&e[i]);
        bad = (v < 0 || v >= (long long)n_nodes);
    }
    unsigned m = __ballot_sync(0xFFFFFFFFu, bad);
    if (m && (threadIdx.x & 31) == 0) atomicOr(&g_flag, 1);
}

// ---------------- Kernel A: per-node precompute ----------------
__global__ __launch_bounds__(256) void node_pre_kernel(
    const float* __restrict__ x,
    const float* __restrict__ W1,
    const float* __restrict__ Wdir,
    int n_nodes)
{
    __shared__ float sWs1[LATENT][HID];
    __shared__ float sWsD[LATENT][EDIM];
    int t = threadIdx.x;
    for (int i = t; i < LATENT * HID; i += 256) {
        int j = i >> 5, k = i & 31;
        sWs1[j][k] = 0.5f * (W1[j * HID + k] + W1[(j + LATENT) * HID + k]);
    }
    for (int i = t; i < LATENT * EDIM; i += 256) {
        int j = i >> 2, c = i & 3;
        sWsD[j][c] = 0.5f * (Wdir[j * EDIM + c] + Wdir[(j + LATENT) * EDIM + c]);
    }
    __syncthreads();

    int warp = t >> 5, lane = t & 31;
    int node = blockIdx.x * 8 + warp;
    if (node >= n_nodes) return;

    const float4* xr = (const float4*)(x + (size_t)node * LATENT);
    float acc0 = 0.f, acc1 = 0.f, accd0 = 0.f, accd1 = 0.f;
    #pragma unroll
    for (int i = 0; i < 16; i += 2) {
        float4 v0 = xr[i], v1 = xr[i + 1];
        int j = i * 4;
        acc0 = fmaf(v0.x, sWs1[j    ][lane], acc0);
        acc0 = fmaf(v0.y, sWs1[j + 1][lane], acc0);
        acc0 = fmaf(v0.z, sWs1[j + 2][lane], acc0);
        acc0 = fmaf(v0.w, sWs1[j + 3][lane], acc0);
        acc1 = fmaf(v1.x, sWs1[j + 4][lane], acc1);
        acc1 = fmaf(v1.y, sWs1[j + 5][lane], acc1);
        acc1 = fmaf(v1.z, sWs1[j + 6][lane], acc1);
        acc1 = fmaf(v1.w, sWs1[j + 7][lane], acc1);
        if (lane < EDIM) {
            accd0 = fmaf(v0.x, sWsD[j    ][lane], accd0);
            accd0 = fmaf(v0.y, sWsD[j + 1][lane], accd0);
            accd0 = fmaf(v0.z, sWsD[j + 2][lane], accd0);
            accd0 = fmaf(v0.w, sWsD[j + 3][lane], accd0);
            accd1 = fmaf(v1.x, sWsD[j + 4][lane], accd1);
            accd1 = fmaf(v1.y, sWsD[j + 5][lane], accd1);
            accd1 = fmaf(v1.z, sWsD[j + 6][lane], accd1);
            accd1 = fmaf(v1.w, sWsD[j + 7][lane], accd1);
        }
    }
    g_P1[(size_t)node * HID + lane] = acc0 + acc1;
    if (lane < EDIM) g_PD[(size_t)node * EDIM + lane] = accd0 + accd1;
}

// ---------------- Edge kernel ----------------
struct Smem {
    float sD  [TILE_E * SD_STRIDE];   // 26112 B
    float sB1 [TILE_E * SH_STRIDE];   // 13824 B
    float sH  [TILE_E * SH_STRIDE];   // 13824 B
    float sBd [TILE_E * EDIM];        //  1536 B
    float sW1T[HID * SD_STRIDE];      //  8704 B
    float sW2T[HID * SH_STRIDE];      //  4608 B
    float sW3P[8 * 16];               //   512 B
    float sWdP[16 * 16];              //  1024 B
    float sb1[HID]; float sb2[HID]; float sbo[EDIM];
    int   sSrc[TILE_E]; int sTgt[TILE_E];
};   // ~70 KB -> 3 CTAs/SM

__global__ __launch_bounds__(256, 3) void edge_kernel(
    const float* __restrict__ x,
    const void*  __restrict__ eidx,
    const float* __restrict__ Wdir, const float* __restrict__ bdir,
    const float* __restrict__ W1,   const float* __restrict__ b1,
    const float* __restrict__ W2,   const float* __restrict__ b2,
    const float* __restrict__ W3,   const float* __restrict__ b3,
    float* __restrict__ out, int n_edges, int n_nodes)
{
    extern __shared__ char smem_raw[];
    Smem* S = (Smem*)smem_raw;
    int t  = threadIdx.x;
    int e0 = blockIdx.x * TILE_E;

    // ---- stage 0: edge indices ----
    if (t < TILE_E) {
        int eg = e0 + t;
        if (eg >= n_edges) eg = n_edges - 1;
        int src, tgt;
        if (g_flag == 0) {
            src = (int)__ldg(&((const long long*)eidx)[eg]);
            tgt = (int)__ldg(&((const long long*)eidx)[(size_t)n_edges + eg]);
        } else {
            src = __ldg(&((const int*)eidx)[eg]);
            tgt = __ldg(&((const int*)eidx)[(size_t)n_edges + eg]);
        }
        S->sSrc[t] = min(max(src, 0), n_nodes - 1);
        S->sTgt[t] = min(max(tgt, 0), n_nodes - 1);
    }
    // ---- stage weights ----
    for (int idx = t; idx < HID * LATENT; idx += 256) {
        int k = idx & 31, j = idx >> 5;
        S->sW1T[k * SD_STRIDE + j] = 0.5f * (W1[(j + LATENT) * HID + k] - W1[j * HID + k]);
    }
    for (int idx = t; idx < HID * HID; idx += 256) {
        int k = idx & 31, j = idx >> 5;
        S->sW2T[k * SH_STRIDE + j] = W2[j * HID + k];
    }
    if (t < 128) {
        int J = t >> 4, c = (t >> 2) & 3, q = (t >> 1) & 1, r = t & 1;
        S->sW3P[t] = W3[(4 * J + 2 * q + r) * EDIM + c];
    }
    {
        int J = t >> 4, c = (t >> 2) & 3, q = (t >> 1) & 1, r = t & 1;
        int j = 4 * J + 2 * q + r;
        S->sWdP[t] = 0.5f * (Wdir[(j + LATENT) * EDIM + c] - Wdir[j * EDIM + c]);
    }
    if (t < HID)  { S->sb1[t] = b1[t]; S->sb2[t] = b2[t]; }
    if (t < EDIM) S->sbo[t] = b3[t] + bdir[t];
    __syncthreads();

    // ---- Phase A: coalesced gathers ----
    {   // x: 16 lanes per edge row
        int c = t & 15, el = t >> 4;          // el in [0,16)
        #pragma unroll
        for (int p = 0; p < 6; p++) {
            int e = el + 16 * p;
            int src = S->sSrc[e], tgt = S->sTgt[e];
            float4 a = *(const float4*)(x + (size_t)src * LATENT + c * 4);
            float4 b = *(const float4*)(x + (size_t)tgt * LATENT + c * 4);
            float4 d;
            d.x = fabsf(a.x - b.x); d.y = fabsf(a.y - b.y);
            d.z = fabsf(a.z - b.z); d.w = fabsf(a.w - b.w);
            *(float4*)&S->sD[e * SD_STRIDE + c * 4] = d;
        }
    }
    {   // P1: 8 lanes per row
        int c = t & 7, el = t >> 3;           // el in [0,32)
        #pragma unroll
        for (int p = 0; p < 3; p++) {
            int e = el + 32 * p;
            int src = S->sSrc[e], tgt = S->sTgt[e];
            float4 a = *(const float4*)(g_P1 + (size_t)src * HID + c * 4);
            float4 b = *(const float4*)(g_P1 + (size_t)tgt * HID + c * 4);
            float4 s; s.x = a.x + b.x; s.y = a.y + b.y; s.z = a.z + b.z; s.w = a.w + b.w;
            *(float4*)&S->sB1[e * SH_STRIDE + c * 4] = s;
        }
    }
    if (t < TILE_E) {   // PD
        int src = S->sSrc[t], tgt = S->sTgt[t];
        float4 a = *(const float4*)(g_PD + (size_t)src * EDIM);
        float4 b = *(const float4*)(g_PD + (size_t)tgt * EDIM);
        float4 s; s.x = a.x + b.x; s.y = a.y + b.y; s.z = a.z + b.z; s.w = a.w + b.w;
        *(float4*)&S->sBd[t * EDIM] = s;
    }
    __syncthreads();

    // GEMM mapping: mg = lane (32 edge groups), ng = warp (8 col groups), M=3
    int mg = t & 31, ng = t >> 5;
    int kc = ng * 4;
    float hk[3][4];

    // ---- Phase B: h1 = relu(sD @ W1diff + base + b1) ----
    {
        unsigned long long acc[3][4];
        #pragma unroll
        for (int m = 0; m < 3; m++) { acc[m][0]=0; acc[m][1]=0; acc[m][2]=0; acc[m][3]=0; }

        #pragma unroll 1
        for (int j4 = 0; j4 < LATENT; j4 += 4) {
            ulonglong2 w0 = *(const ulonglong2*)&S->sW1T[(kc + 0) * SD_STRIDE + j4];
            ulonglong2 w1 = *(const ulonglong2*)&S->sW1T[(kc + 1) * SD_STRIDE + j4];
            ulonglong2 w2 = *(const ulonglong2*)&S->sW1T[(kc + 2) * SD_STRIDE + j4];
            ulonglong2 w3 = *(const ulonglong2*)&S->sW1T[(kc + 3) * SD_STRIDE + j4];
            #pragma unroll
            for (int m = 0; m < 3; m++) {
                int e = mg + 32 * m;
                ulonglong2 d = *(const ulonglong2*)&S->sD[e * SD_STRIDE + j4];
                ffma2(acc[m][0], d.x, w0.x); ffma2(acc[m][0], d.y, w0.y);
                ffma2(acc[m][1], d.x, w1.x); ffma2(acc[m][1], d.y, w1.y);
                ffma2(acc[m][2], d.x, w2.x); ffma2(acc[m][2], d.y, w2.y);
                ffma2(acc[m][3], d.x, w3.x); ffma2(acc[m][3], d.y, w3.y);
            }
        }
        float bb0 = S->sb1[kc], bb1 = S->sb1[kc+1], bb2 = S->sb1[kc+2], bb3 = S->sb1[kc+3];
        #pragma unroll
        for (int m = 0; m < 3; m++) {
            int e = mg + 32 * m;
            float4 base = *(const float4*)&S->sB1[e * SH_STRIDE + kc];
            float2 r0 = unpack2(acc[m][0]);
            float2 r1 = unpack2(acc[m][1]);
            float2 r2 = unpack2(acc[m][2]);
            float2 r3 = unpack2(acc[m][3]);
            float4 hv;
            hv.x = fmaxf(r0.x + r0.y + base.x + bb0, 0.f);
            hv.y = fmaxf(r1.x + r1.y + base.y + bb1, 0.f);
            hv.z = fmaxf(r2.x + r2.y + base.z + bb2, 0.f);
            hv.w = fmaxf(r3.x + r3.y + base.w + bb3, 0.f);
            hk[m][0] = hv.x; hk[m][1] = hv.y; hk[m][2] = hv.z; hk[m][3] = hv.w;
            *(float4*)&S->sH[e * SH_STRIDE + kc] = hv;
        }
    }
    __syncthreads();

    // ---- Phase C: H2 = relu(h1 @ W2 + b2 + h1) -> sB1 ----
    {
        unsigned long long acc[3][4];
        #pragma unroll
        for (int m = 0; m < 3; m++) { acc[m][0]=0; acc[m][1]=0; acc[m][2]=0; acc[m][3]=0; }

        #pragma unroll 1
        for (int j4 = 0; j4 < HID; j4 += 4) {
            ulonglong2 w0 = *(const ulonglong2*)&S->sW2T[(kc + 0) * SH_STRIDE + j4];
            ulonglong2 w1 = *(const ulonglong2*)&S->sW2T[(kc + 1) * SH_STRIDE + j4];
            ulonglong2 w2 = *(const ulonglong2*)&S->sW2T[(kc + 2) * SH_STRIDE + j4];
            ulonglong2 w3 = *(const ulonglong2*)&S->sW2T[(kc + 3) * SH_STRIDE + j4];
            #pragma unroll
            for (int m = 0; m < 3; m++) {
                int e = mg + 32 * m;
                ulonglong2 h = *(const ulonglong2*)&S->sH[e * SH_STRIDE + j4];
                ffma2(acc[m][0], h.x, w0.x); ffma2(acc[m][0], h.y, w0.y);
                ffma2(acc[m][1], h.x, w1.x); ffma2(acc[m][1], h.y, w1.y);
                ffma2(acc[m][2], h.x, w2.x); ffma2(acc[m][2], h.y, w2.y);
                ffma2(acc[m][3], h.x, w3.x); ffma2(acc[m][3], h.y, w3.y);
            }
        }
        float bb0 = S->sb2[kc], bb1 = S->sb2[kc+1], bb2 = S->sb2[kc+2], bb3 = S->sb2[kc+3];
        #pragma unroll
        for (int m = 0; m < 3; m++) {
            int e = mg + 32 * m;
            float2 r0 = unpack2(acc[m][0]);
            float2 r1 = unpack2(acc[m][1]);
            float2 r2 = unpack2(acc[m][2]);
            float2 r3 = unpack2(acc[m][3]);
            float4 hv;
            hv.x = fmaxf(r0.x + r0.y + hk[m][0] + bb0, 0.f);
            hv.y = fmaxf(r1.x + r1.y + hk[m][1] + bb1, 0.f);
            hv.z = fmaxf(r2.x + r2.y + hk[m][2] + bb2, 0.f);
            hv.w = fmaxf(r3.x + r3.y + hk[m][3] + bb3, 0.f);
            *(float4*)&S->sB1[e * SH_STRIDE + kc] = hv;
        }
    }
    __syncthreads();

    // ---- Phase D: 2 threads per edge, 2 cols each (threads 0..191) ----
    if (t < 2 * TILE_E) {
        int e  = t >> 1;
        int c0 = (t & 1) * 2;
        unsigned long long acc[2] = {0ull, 0ull};
        #pragma unroll
        for (int J = 0; J < 8; J++) {
            ulonglong2 h  = *(const ulonglong2*)&S->sB1[e * SH_STRIDE + 4 * J];
            ulonglong2 wA = *(const ulonglong2*)&S->sW3P[J * 16 + c0 * 4];
            ulonglong2 wB = *(const ulonglong2*)&S->sW3P[J * 16 + (c0 + 1) * 4];
            ffma2(acc[0], h.x, wA.x); ffma2(acc[0], h.y, wA.y);
            ffma2(acc[1], h.x, wB.x); ffma2(acc[1], h.y, wB.y);
        }
        #pragma unroll
        for (int J = 0; J < 16; J++) {
            ulonglong2 d  = *(const ulonglong2*)&S->sD[e * SD_STRIDE + 4 * J];
            ulonglong2 wA = *(const ulonglong2*)&S->sWdP[J * 16 + c0 * 4];
            ulonglong2 wB = *(const ulonglong2*)&S->sWdP[J * 16 + (c0 + 1) * 4];
            ffma2(acc[0], d.x, wA.x); ffma2(acc[0], d.y, wA.y);
            ffma2(acc[1], d.x, wB.x); ffma2(acc[1], d.y, wB.y);
        }
        float2 r0 = unpack2(acc[0]);
        float2 r1 = unpack2(acc[1]);
        int eg = e0 + e;
        if (eg < n_edges) {
            float2 o;
            o.x = r0.x + r0.y + S->sbo[c0    ] + S->sBd[e * EDIM + c0];
            o.y = r1.x + r1.y + S->sbo[c0 + 1] + S->sBd[e * EDIM + c0 + 1];
            *(float2*)(out + (size_t)eg * EDIM + c0) = o;
        }
    }
}

extern "C" void kernel_launch(void* const* d_in, const int* in_sizes, int n_in,
                              void* d_out, int out_size)
{
    const float* x    = (const float*)d_in[0];
    const void*  eidx = d_in[1];
    const float* Wdir = (const float*)d_in[2];
    const float* bdir = (const float*)d_in[3];
    const float* W1   = (const float*)d_in[4];
    const float* b1   = (const float*)d_in[5];
    const float* W2   = (const float*)d_in[6];
    const float* b2   = (const float*)d_in[7];
    const float* W3   = (const float*)d_in[8];
    const float* b3   = (const float*)d_in[9];
    float* out = (float*)d_out;

    int n_nodes = in_sizes[0] / LATENT;
    int n_edges = in_sizes[1] / 2;

    int n_probe = n_edges < 32768 ? n_edges : 32768;
    reset_flag_kernel<<<1, 1>>>();
    probe_kernel<<<(n_probe + 255) / 256, 256>>>((const long long*)eidx, n_probe, n_nodes);

    node_pre_kernel<<<(n_nodes + 7) / 8, 256>>>(x, W1, Wdir, n_nodes);

    cudaFuncSetAttribute(edge_kernel, cudaFuncAttributeMaxDynamicSharedMemorySize,
                         (int)sizeof(Smem));
    int nblk = (n_edges + TILE_E - 1) / TILE_E;
    edge_kernel<<<nblk, 256, sizeof(Smem)>>>(x, eidx, Wdir, bdir, W1, b1, W2, b2,
                                             W3, b3, out, n_edges, n_nodes);
}